// round 2
// baseline (speedup 1.0000x reference)
#include <cuda_runtime.h>
#include <cuda_bf16.h>

// Problem constants
#define B_   2
#define N1_  500
#define N2_  800
#define D_   128
#define PB_  (B_ * N1_ * N2_)   // 800000 elements per output tensor

// Scratch for projections (allocation-free rule: __device__ globals)
__device__ float g_p1[B_ * N1_ * D_];   // p1 = h1 @ W1[:D] + b1   [B,N1,D]
__device__ float g_p2[B_ * N2_ * D_];   // p2 = h2 @ W1[D:]        [B,N2,D]

// ---------------- f32x2 packed-math helpers (Blackwell) ----------------
__device__ __forceinline__ unsigned long long pk2(float lo, float hi) {
    unsigned long long r;
    asm("mov.b64 %0, {%1,%2};" : "=l"(r) : "f"(lo), "f"(hi));
    return r;
}
__device__ __forceinline__ void unpk2(unsigned long long v, float& lo, float& hi) {
    asm("mov.b64 {%0,%1}, %2;" : "=f"(lo), "=f"(hi) : "l"(v));
}
__device__ __forceinline__ unsigned long long add2_(unsigned long long a, unsigned long long b) {
    unsigned long long r;
    asm("add.rn.f32x2 %0, %1, %2;" : "=l"(r) : "l"(a), "l"(b));
    return r;
}
__device__ __forceinline__ unsigned long long fma2_(unsigned long long a, unsigned long long b, unsigned long long c) {
    unsigned long long r;
    asm("fma.rn.f32x2 %0, %1, %2, %3;" : "=l"(r) : "l"(a), "l"(b), "l"(c));
    return r;
}

// ---------------- Kernel 1: projections ----------------
// Blocks 0..62   : p1 rows  (1000 rows = B*N1), W = W1[0:128], +b1
// Blocks 63..162 : p2 rows  (1600 rows = B*N2), W = W1[128:256]
// Block: dim3(64,4) = 256 threads, 16 rows per block, each ty handles 4 rows.
// Each thread owns one d-pair (2*tx, 2*tx+1), accumulates with fma.rn.f32x2.
__global__ __launch_bounds__(256) void proj_kernel(
    const float* __restrict__ h1, const float* __restrict__ h2,
    const float* __restrict__ W1, const float* __restrict__ b1)
{
    const int tx = threadIdx.x;           // 0..63  (d-pair)
    const int ty = threadIdx.y;           // 0..3
    __shared__ __align__(16) float sh[16][128];

    const bool isP1 = (blockIdx.x < 63);
    const int row0 = isP1 ? blockIdx.x * 16 : (blockIdx.x - 63) * 16;
    const int nrows = isP1 ? (B_ * N1_) : (B_ * N2_);
    const float* __restrict__ src = isP1 ? h1 : h2;
    const float* __restrict__ W   = W1 + (isP1 ? 0 : D_ * D_);
    float* __restrict__ dst       = isP1 ? g_p1 : g_p2;

    // cooperative load of up to 16 rows (zero-fill invalid)
    const int t = ty * 64 + tx;           // 0..255
#pragma unroll
    for (int it = 0; it < 2; it++) {
        int idx = t + it * 256;           // float4 index, 512 total
        int r  = idx >> 5;                // 32 float4 per row
        int cc = idx & 31;
        float4 v = make_float4(0.f, 0.f, 0.f, 0.f);
        if (row0 + r < nrows) v = *(const float4*)&src[(size_t)(row0 + r) * D_ + cc * 4];
        *(float4*)&sh[r][cc * 4] = v;
    }
    __syncthreads();

    unsigned long long acc[4];
    float bx = 0.f, by = 0.f;
    if (isP1) { float2 bb = *(const float2*)&b1[2 * tx]; bx = bb.x; by = bb.y; }
#pragma unroll
    for (int rr = 0; rr < 4; rr++) acc[rr] = pk2(bx, by);

#pragma unroll 4
    for (int k = 0; k < D_; k++) {
        float2 w = *(const float2*)&W[k * D_ + 2 * tx];
        unsigned long long wp = pk2(w.x, w.y);
#pragma unroll
        for (int rr = 0; rr < 4; rr++) {
            float h = sh[ty + 4 * rr][k];
            acc[rr] = fma2_(pk2(h, h), wp, acc[rr]);
        }
    }

#pragma unroll
    for (int rr = 0; rr < 4; rr++) {
        int r = row0 + ty + 4 * rr;
        if (r < nrows) {
            float lo, hi; unpk2(acc[rr], lo, hi);
            float2 o; o.x = lo; o.y = hi;
            *(float2*)&dst[(size_t)r * D_ + 2 * tx] = o;
        }
    }
}

// ---------------- Kernel 2: pairwise relu-reduction + epilogue ----------------
// Grid: (13 m-tiles, 8 n-tiles, B). Block 16x16, each thread 4x4 outputs.
// d processed in 2 chunks of 64 via shared tiles, packed f32x2 math.
#define PAD_ 66   // floats per row in smem: 66 mod 32 = 2 -> conflict-free LDS.64

__global__ __launch_bounds__(256) void pair_kernel(
    const float* __restrict__ contact,
    const int* __restrict__ S1, const int* __restrict__ S2,
    const float* __restrict__ W2, const float* __restrict__ b2,
    float* __restrict__ out)
{
    __shared__ __align__(16) float sP1[64 * PAD_];
    __shared__ __align__(16) float sP2[64 * PAD_];
    __shared__ __align__(16) float sW2[D_];

    const int tx = threadIdx.x;   // 0..15 -> m
    const int ty = threadIdx.y;   // 0..15 -> n
    const int t  = ty * 16 + tx;
    const int b  = blockIdx.z;
    const int n0 = blockIdx.y * 64;
    const int m0 = blockIdx.x * 64;

    if (t < 64) {
        float2 w = *(const float2*)&W2[2 * t];
        *(float2*)&sW2[2 * t] = w;
    }

    unsigned long long acc[4][4];
#pragma unroll
    for (int i = 0; i < 4; i++)
#pragma unroll
        for (int j = 0; j < 4; j++) acc[i][j] = pk2(0.f, 0.f);

    const float* __restrict__ p1base = g_p1 + ((size_t)b * N1_ + n0) * D_;
    const float* __restrict__ p2base = g_p2 + ((size_t)b * N2_ + m0) * D_;

    for (int c = 0; c < 2; c++) {
        if (c) __syncthreads();   // protect previous chunk reads
        // cooperative load: 64 rows x 32 d-pairs each array
#pragma unroll
        for (int it = 0; it < 8; it++) {
            int idx = t + it * 256;      // 0..2047
            int n  = idx >> 5;           // row in tile
            int d2 = idx & 31;           // d-pair in chunk
            float2 a = make_float2(0.f, 0.f);
            if (n0 + n < N1_) a = *(const float2*)&p1base[n * D_ + c * 64 + d2 * 2];
            *(float2*)&sP1[n * PAD_ + d2 * 2] = a;
            float2 bb = make_float2(0.f, 0.f);
            if (m0 + n < N2_) bb = *(const float2*)&p2base[n * D_ + c * 64 + d2 * 2];
            *(float2*)&sP2[n * PAD_ + d2 * 2] = bb;
        }
        __syncthreads();

#pragma unroll 8
        for (int d2 = 0; d2 < 32; d2++) {
            unsigned long long w2p = *(const unsigned long long*)&sW2[c * 64 + d2 * 2];
            unsigned long long a[4], bv[4];
#pragma unroll
            for (int i = 0; i < 4; i++)
                a[i] = *(const unsigned long long*)&sP1[(ty + 16 * i) * PAD_ + 2 * d2];
#pragma unroll
            for (int j = 0; j < 4; j++)
                bv[j] = *(const unsigned long long*)&sP2[(tx + 16 * j) * PAD_ + 2 * d2];
#pragma unroll
            for (int i = 0; i < 4; i++) {
#pragma unroll
                for (int j = 0; j < 4; j++) {
                    unsigned long long s = add2_(a[i], bv[j]);
                    float lo, hi; unpk2(s, lo, hi);
                    lo = fmaxf(lo, 0.f);
                    hi = fmaxf(hi, 0.f);
                    acc[i][j] = fma2_(pk2(lo, hi), w2p, acc[i][j]);
                }
            }
        }
    }

    // epilogue: pred / y_contact / mask
    const float b2v = b2[0];
    float m1v[4], m2v[4];
    int nn[4], mm[4];
#pragma unroll
    for (int i = 0; i < 4; i++) {
        nn[i] = n0 + ty + 16 * i;
        m1v[i] = (nn[i] < N1_ && S1[b * N1_ + nn[i]] != 0) ? 1.f : 0.f;
    }
#pragma unroll
    for (int j = 0; j < 4; j++) {
        mm[j] = m0 + tx + 16 * j;
        m2v[j] = (mm[j] < N2_ && S2[b * N2_ + mm[j]] != 0) ? 1.f : 0.f;
    }
#pragma unroll
    for (int i = 0; i < 4; i++) {
#pragma unroll
        for (int j = 0; j < 4; j++) {
            if (nn[i] < N1_ && mm[j] < N2_) {
                int idx = b * (N1_ * N2_) + nn[i] * N2_ + mm[j];
                float lo, hi; unpk2(acc[i][j], lo, hi);
                out[idx] = lo + hi + b2v;                       // pred
                float mk = m1v[i] * m2v[j];
                float ct = contact[idx];
                out[PB_ + idx]     = (ct < 0.5f) ? mk : 0.f;    // y_contact
                out[2 * PB_ + idx] = mk;                        // mask
            }
        }
    }
}

extern "C" void kernel_launch(void* const* d_in, const int* in_sizes, int n_in,
                              void* d_out, int out_size) {
    const int*   S1      = (const int*)d_in[0];    // [B,N1]
    const int*   S2      = (const int*)d_in[1];    // [B,N2]
    const float* h1      = (const float*)d_in[2];  // [B,N1,D]
    const float* h2      = (const float*)d_in[3];  // [B,N2,D]
    const float* contact = (const float*)d_in[4];  // [B,N1,N2]
    const float* W1      = (const float*)d_in[5];  // [2D,D]
    const float* b1      = (const float*)d_in[6];  // [D]
    const float* W2      = (const float*)d_in[7];  // [D,1]
    const float* b2      = (const float*)d_in[8];  // [1]
    float* out = (float*)d_out;

    (void)in_sizes; (void)n_in; (void)out_size;

    proj_kernel<<<163, dim3(64, 4)>>>(h1, h2, W1, b1);
    pair_kernel<<<dim3(13, 8, 2), dim3(16, 16)>>>(contact, S1, S2, W2, b2, out);
}

// round 7
// speedup vs baseline: 1.2012x; 1.2012x over previous
#include <cuda_runtime.h>
#include <cuda_bf16.h>

// Problem constants
#define B_   2
#define N1_  500
#define N2_  800
#define D_   128
#define PB_  (B_ * N1_ * N2_)   // 800000 elements per output tensor

// Scratch for projections (allocation-free rule: __device__ globals)
__device__ float g_p1[B_ * N1_ * D_];   // p1 = h1 @ W1[:D] + b1   [B,N1,D]
__device__ float g_p2[B_ * N2_ * D_];   // p2 = h2 @ W1[D:]        [B,N2,D]

// ---------------- f32x2 packed-math helpers (Blackwell) ----------------
__device__ __forceinline__ unsigned long long pk2(float lo, float hi) {
    unsigned long long r;
    asm("mov.b64 %0, {%1,%2};" : "=l"(r) : "f"(lo), "f"(hi));
    return r;
}
__device__ __forceinline__ void unpk2(unsigned long long v, float& lo, float& hi) {
    asm("mov.b64 {%0,%1}, %2;" : "=f"(lo), "=f"(hi) : "l"(v));
}
__device__ __forceinline__ unsigned long long add2_(unsigned long long a, unsigned long long b) {
    unsigned long long r;
    asm("add.rn.f32x2 %0, %1, %2;" : "=l"(r) : "l"(a), "l"(b));
    return r;
}
__device__ __forceinline__ unsigned long long fma2_(unsigned long long a, unsigned long long b, unsigned long long c) {
    unsigned long long r;
    asm("fma.rn.f32x2 %0, %1, %2, %3;" : "=l"(r) : "l"(a), "l"(b), "l"(c));
    return r;
}

// ---------------- Kernel 1: projections ----------------
__global__ __launch_bounds__(256) void proj_kernel(
    const float* __restrict__ h1, const float* __restrict__ h2,
    const float* __restrict__ W1, const float* __restrict__ b1)
{
    const int tx = threadIdx.x;           // 0..63  (d-pair)
    const int ty = threadIdx.y;           // 0..3
    __shared__ __align__(16) float sh[16][128];

    const bool isP1 = (blockIdx.x < 63);
    const int row0 = isP1 ? blockIdx.x * 16 : (blockIdx.x - 63) * 16;
    const int nrows = isP1 ? (B_ * N1_) : (B_ * N2_);
    const float* __restrict__ src = isP1 ? h1 : h2;
    const float* __restrict__ W   = W1 + (isP1 ? 0 : D_ * D_);
    float* __restrict__ dst       = isP1 ? g_p1 : g_p2;

    const int t = ty * 64 + tx;           // 0..255
#pragma unroll
    for (int it = 0; it < 2; it++) {
        int idx = t + it * 256;           // float4 index, 512 total
        int r  = idx >> 5;                // 32 float4 per row
        int cc = idx & 31;
        float4 v = make_float4(0.f, 0.f, 0.f, 0.f);
        if (row0 + r < nrows) v = *(const float4*)&src[(size_t)(row0 + r) * D_ + cc * 4];
        *(float4*)&sh[r][cc * 4] = v;
    }
    __syncthreads();

    unsigned long long acc[4];
    float bx = 0.f, by = 0.f;
    if (isP1) { float2 bb = *(const float2*)&b1[2 * tx]; bx = bb.x; by = bb.y; }
#pragma unroll
    for (int rr = 0; rr < 4; rr++) acc[rr] = pk2(bx, by);

#pragma unroll 4
    for (int k = 0; k < D_; k++) {
        float2 w = *(const float2*)&W[k * D_ + 2 * tx];
        unsigned long long wp = pk2(w.x, w.y);
#pragma unroll
        for (int rr = 0; rr < 4; rr++) {
            float h = sh[ty + 4 * rr][k];
            acc[rr] = fma2_(pk2(h, h), wp, acc[rr]);
        }
    }

#pragma unroll
    for (int rr = 0; rr < 4; rr++) {
        int r = row0 + ty + 4 * rr;
        if (r < nrows) {
            float lo, hi; unpk2(acc[rr], lo, hi);
            float2 o; o.x = lo; o.y = hi;
            *(float2*)&dst[(size_t)r * D_ + 2 * tx] = o;
        }
    }
}

// ---------------- Kernel 2: pairwise relu-reduction + epilogue ----------------
// Tiles: 32 (n, N1) x 64 (m, N2). Grid (13 m-tiles, 16 n-tiles, B) = 416 blocks.
// Block 16x16 = 256 threads; each thread computes 2(n) x 4(m) outputs.
// Full D=128 kept in shared (one load phase, one sync). Packed f32x2 math.
// PAD_=130: words/row = 65 (odd, ==1 mod 16) -> conflict-free LDS.64 for the
// 16-distinct-row sP2 reads; sP1 reads broadcast within a half-warp.
// Smem stores are STS.64 only (row byte stride 520 == 0 mod 8, NOT mod 16).
#define PAD_ 130

__global__ __launch_bounds__(256) void pair_kernel(
    const float* __restrict__ contact,
    const int* __restrict__ S1, const int* __restrict__ S2,
    const float* __restrict__ W2, const float* __restrict__ b2,
    float* __restrict__ out)
{
    __shared__ __align__(16) float sP1[32 * PAD_];
    __shared__ __align__(16) float sP2[64 * PAD_];
    __shared__ __align__(16) float sW2[D_];

    const int tx = threadIdx.x;   // 0..15 -> m
    const int ty = threadIdx.y;   // 0..15 -> n
    const int t  = ty * 16 + tx;
    const int b  = blockIdx.z;
    const int n0 = blockIdx.y * 32;
    const int m0 = blockIdx.x * 64;

    const float* __restrict__ p1base = g_p1 + ((size_t)b * N1_ + n0) * D_;
    const float* __restrict__ p2base = g_p2 + ((size_t)b * N2_ + m0) * D_;

    // ---- load phase ----
    if (t < 64) {
        float2 w = *(const float2*)&W2[2 * t];
        *(float2*)&sW2[2 * t] = w;
    }
    // sP1: 32 rows x 32 float4 = 1024 float4, 4 per thread (LDG.128 -> 2x STS.64)
#pragma unroll
    for (int it = 0; it < 4; it++) {
        int idx = t + it * 256;
        int r  = idx >> 5;
        int cc = idx & 31;
        float4 v = make_float4(0.f, 0.f, 0.f, 0.f);
        if (n0 + r < N1_) v = *(const float4*)&p1base[r * D_ + cc * 4];
        float* s = &sP1[r * PAD_ + cc * 4];
        *(float2*)(s)     = make_float2(v.x, v.y);
        *(float2*)(s + 2) = make_float2(v.z, v.w);
    }
    // sP2: 64 rows x 32 float4 = 2048 float4, 8 per thread
#pragma unroll
    for (int it = 0; it < 8; it++) {
        int idx = t + it * 256;
        int r  = idx >> 5;
        int cc = idx & 31;
        float4 v = make_float4(0.f, 0.f, 0.f, 0.f);
        if (m0 + r < N2_) v = *(const float4*)&p2base[r * D_ + cc * 4];
        float* s = &sP2[r * PAD_ + cc * 4];
        *(float2*)(s)     = make_float2(v.x, v.y);
        *(float2*)(s + 2) = make_float2(v.z, v.w);
    }
    __syncthreads();

    // ---- mainloop over 64 packed d-pairs ----
    unsigned long long acc[2][4];
#pragma unroll
    for (int i = 0; i < 2; i++)
#pragma unroll
        for (int j = 0; j < 4; j++) acc[i][j] = pk2(0.f, 0.f);

#pragma unroll 2
    for (int d2 = 0; d2 < 64; d2++) {
        unsigned long long w2p = *(const unsigned long long*)&sW2[2 * d2];
        unsigned long long a[2], bv[4];
#pragma unroll
        for (int i = 0; i < 2; i++)
            a[i] = *(const unsigned long long*)&sP1[(ty + 16 * i) * PAD_ + 2 * d2];
#pragma unroll
        for (int j = 0; j < 4; j++)
            bv[j] = *(const unsigned long long*)&sP2[(tx + 16 * j) * PAD_ + 2 * d2];
#pragma unroll
        for (int i = 0; i < 2; i++) {
#pragma unroll
            for (int j = 0; j < 4; j++) {
                unsigned long long s = add2_(a[i], bv[j]);
                float lo, hi; unpk2(s, lo, hi);
                lo = fmaxf(lo, 0.f);
                hi = fmaxf(hi, 0.f);
                acc[i][j] = fma2_(pk2(lo, hi), w2p, acc[i][j]);
            }
        }
    }

    // ---- epilogue: pred / y_contact / mask ----
    const float b2v = b2[0];
    float m1v[2], m2v[4];
    int nn[2], mm[4];
#pragma unroll
    for (int i = 0; i < 2; i++) {
        nn[i] = n0 + ty + 16 * i;
        m1v[i] = (nn[i] < N1_ && S1[b * N1_ + nn[i]] != 0) ? 1.f : 0.f;
    }
#pragma unroll
    for (int j = 0; j < 4; j++) {
        mm[j] = m0 + tx + 16 * j;
        m2v[j] = (mm[j] < N2_ && S2[b * N2_ + mm[j]] != 0) ? 1.f : 0.f;
    }
#pragma unroll
    for (int i = 0; i < 2; i++) {
#pragma unroll
        for (int j = 0; j < 4; j++) {
            if (nn[i] < N1_ && mm[j] < N2_) {
                int idx = b * (N1_ * N2_) + nn[i] * N2_ + mm[j];
                float lo, hi; unpk2(acc[i][j], lo, hi);
                out[idx] = lo + hi + b2v;                       // pred
                float mk = m1v[i] * m2v[j];
                float ct = contact[idx];
                out[PB_ + idx]     = (ct < 0.5f) ? mk : 0.f;    // y_contact
                out[2 * PB_ + idx] = mk;                        // mask
            }
        }
    }
}

extern "C" void kernel_launch(void* const* d_in, const int* in_sizes, int n_in,
                              void* d_out, int out_size) {
    const int*   S1      = (const int*)d_in[0];    // [B,N1]
    const int*   S2      = (const int*)d_in[1];    // [B,N2]
    const float* h1      = (const float*)d_in[2];  // [B,N1,D]
    const float* h2      = (const float*)d_in[3];  // [B,N2,D]
    const float* contact = (const float*)d_in[4];  // [B,N1,N2]
    const float* W1      = (const float*)d_in[5];  // [2D,D]
    const float* b1      = (const float*)d_in[6];  // [D]
    const float* W2      = (const float*)d_in[7];  // [D,1]
    const float* b2      = (const float*)d_in[8];  // [1]
    float* out = (float*)d_out;

    (void)in_sizes; (void)n_in; (void)out_size;

    proj_kernel<<<163, dim3(64, 4)>>>(h1, h2, W1, b1);
    pair_kernel<<<dim3(13, 16, 2), dim3(16, 16)>>>(contact, S1, S2, W2, b2, out);
}